// round 15
// baseline (speedup 1.0000x reference)
#include <cuda_runtime.h>
#include <math.h>
#include <stdint.h>

#define NTASK   2000
#define NSUP    25
#define NQ      75
#define DIM     640
#define KW      5
#define NLAYERS 20
#define R       80
#define DC      64
#define NCHUNK  (DIM / DC)
#define PADC    68           // 16B-aligned rows for cp.async (R13 layout)
#define PADG    81
#define PADU    8
#define EPS     1e-6f
#define NTHR    256
#define NTILES  136

#define ZX_FLOATS  (R * PADC)       // 5440
#define SUP_FLOATS (NSUP * PADC)    // 1700
#define G_OFF      (2 * ZX_FLOATS + 2 * SUP_FLOATS)
#define SMEM_FLOATS (G_OFF + R * PADG)
#define SMEM_BYTES  (SMEM_FLOATS * 4)   // 83040

__device__ __forceinline__ void cpa16(uint32_t dst, const float* src) {
    asm volatile("cp.async.cg.shared.global [%0], [%1], 16;" :: "r"(dst), "l"(src));
}

__global__ __launch_bounds__(NTHR, 2)
void fewshot_kernel(const float* __restrict__ Zs_g,
                    const int*   __restrict__ Y_g,
                    const float* __restrict__ Zq_g,
                    const float* __restrict__ t1_p,
                    const float* __restrict__ gm_p,
                    const float* __restrict__ t2_p,
                    float*       __restrict__ out)
{
    extern __shared__ __align__(16) float smem[];
    float* ZxB[2]  = { smem, smem + ZX_FLOATS };
    float* SupB[2] = { smem + 2 * ZX_FLOATS, smem + 2 * ZX_FLOATS + SUP_FLOATS };
    float* G       = smem + G_OFF;
    float* U_s     = smem;              // aliases ZxB[0] in phase 2

    __shared__ float red_s[3][2 * KW];  // per-warp partials: [usum x5, n x5]
    __shared__ int   Y_sh[NSUP];

    const int b = blockIdx.x;
    const int t = threadIdx.x;

    const float c      = log1pf(expf(t1_p[0]));
    const float c2     = c * c;
    const float g      = log1pf(expf(gm_p[0]));
    const float inv_t2 = 1.0f / (log1pf(expf(t2_p[0])) + 1.0f);

    if (t < NSUP) Y_sh[t] = Y_g[b * NSUP + t];

    const uint32_t zx_u32[2]  = { (uint32_t)__cvta_generic_to_shared(ZxB[0]),
                                  (uint32_t)__cvta_generic_to_shared(ZxB[1]) };
    const uint32_t sup_u32[2] = { (uint32_t)__cvta_generic_to_shared(SupB[0]),
                                  (uint32_t)__cvta_generic_to_shared(SupB[1]) };

    const float* Zq_b = Zq_g + (size_t)b * NQ   * DIM;
    const float* Zs_b = Zs_g + (size_t)b * NSUP * DIM;

    // symmetric tile unrank (upper triangle of 16x16 grid of 5x5 tiles)
    const bool act = (t < NTILES);
    int ti = 0, tj = 0;
    {
        int rem = act ? t : 0;
        #pragma unroll
        for (int r = 0; r < 16; r++)
            if (rem >= 16 - ti) { rem -= 16 - ti; ti++; }
        tj = ti + rem;
    }
    const int ri = ti * 5, rj = tj * 5;

    unsigned long long acc[25];
    #pragma unroll
    for (int i = 0; i < 25; i++) acc[i] = 0ull;

    // ---- stage chunk 0 ----
    {
        for (int idx = t; idx < NQ * 16; idx += NTHR) {
            const int row = idx >> 4, v = idx & 15;
            cpa16(zx_u32[0] + (row * PADC + 4 * v) * 4, Zq_b + row * DIM + 4 * v);
        }
        for (int idx = t; idx < NSUP * 16; idx += NTHR) {
            const int row = idx >> 4, v = idx & 15;
            cpa16(sup_u32[0] + (row * PADC + 4 * v) * 4, Zs_b + row * DIM + 4 * v);
        }
        asm volatile("cp.async.commit_group;");
    }

    for (int ch = 0; ch < NCHUNK; ch++) {
        const int cur = ch & 1, nxt = (ch + 1) & 1;
        if (ch + 1 < NCHUNK) {
            const int d0 = (ch + 1) * DC;
            for (int idx = t; idx < NQ * 16; idx += NTHR) {
                const int row = idx >> 4, v = idx & 15;
                cpa16(zx_u32[nxt] + (row * PADC + 4 * v) * 4, Zq_b + row * DIM + d0 + 4 * v);
            }
            for (int idx = t; idx < NSUP * 16; idx += NTHR) {
                const int row = idx >> 4, v = idx & 15;
                cpa16(sup_u32[nxt] + (row * PADC + 4 * v) * 4, Zs_b + row * DIM + d0 + 4 * v);
            }
        }
        asm volatile("cp.async.commit_group;");
        asm volatile("cp.async.wait_group 1;");
        __syncthreads();

        float* Zx  = ZxB[cur];
        float* Sup = SupB[cur];
        for (int idx = t; idx < KW * DC; idx += NTHR) {
            const int dl = idx & (DC - 1);
            const int k  = idx / DC;
            float s = 0.f;
            #pragma unroll
            for (int j = 0; j < NSUP; j++)
                if (Y_sh[j] == k) s += Sup[j * PADC + dl];
            Zx[(NQ + k) * PADC + dl] = s;
        }
        __syncthreads();

        if (act) {
            #pragma unroll 4
            for (int dl = 0; dl < DC; dl += 2) {
                unsigned long long av[5], bv[5];
                #pragma unroll
                for (int i = 0; i < 5; i++)
                    av[i] = *(const unsigned long long*)&Zx[(ri + i) * PADC + dl];
                #pragma unroll
                for (int j = 0; j < 5; j++)
                    bv[j] = *(const unsigned long long*)&Zx[(rj + j) * PADC + dl];
                #pragma unroll
                for (int i = 0; i < 5; i++)
                    #pragma unroll
                    for (int j = 0; j < 5; j++)
                        asm("fma.rn.f32x2 %0, %1, %2, %0;"
                            : "+l"(acc[i * 5 + j]) : "l"(av[i]), "l"(bv[j]));
            }
        }
        __syncthreads();
    }

    if (act) {
        #pragma unroll
        for (int i = 0; i < 5; i++)
            #pragma unroll
            for (int j = 0; j < 5; j++) {
                const unsigned long long x = acc[i * 5 + j];
                const float lo = __uint_as_float((unsigned)(x & 0xffffffffu));
                const float hi = __uint_as_float((unsigned)(x >> 32));
                const float v  = (lo + hi) * c2;
                G[(ri + i) * PADG + (rj + j)] = v;
                G[(rj + j) * PADG + (ri + i)] = v;
            }
    }
    __syncthreads();

    // ---- Phase 2: all per-class state in registers, 2 barriers/layer ----
    const int q    = t;
    const int w    = t >> 5;
    const int lane = t & 31;

    float cnt_r[KW], ssq_r[KW], invden_r[KW], halfnn_r[KW], gV_r[KW];
    float sk[KW], gu[KW];
    #pragma unroll
    for (int k = 0; k < KW; k++) {
        float cn = 0.f;
        #pragma unroll
        for (int j = 0; j < NSUP; j++) cn += (Y_sh[j] == k) ? 1.f : 0.f;
        cnt_r[k] = cn;
        ssq_r[k] = G[(NQ + k) * PADG + (NQ + k)];
        const float iv = 1.0f / cn;
        invden_r[k] = iv;
        halfnn_r[k] = 0.5f * ssq_r[k] * iv * iv;
        gV_r[k]     = g;
        gu[k]       = 0.f;
        sk[k]       = (q < NQ) ? G[(NQ + k) * PADG + q] : 0.f;
    }

    for (int it = 0; it < NLAYERS; it++) {
        float u[KW];
        #pragma unroll
        for (int k = 0; k < KW; k++) u[k] = 0.f;

        if (q < NQ) {
            float a[KW], m = -1e30f;
            #pragma unroll
            for (int k = 0; k < KW; k++) {
                a[k] = inv_t2 * ((gu[k] + sk[k]) * invden_r[k] - halfnn_r[k] + gV_r[k]);
                m = fmaxf(m, a[k]);
            }
            float ssum = 0.f;
            #pragma unroll
            for (int k = 0; k < KW; k++) { u[k] = __expf(a[k] - m); ssum += u[k]; }
            const float r = 1.0f / ssum;
            #pragma unroll
            for (int k = 0; k < KW; k++) u[k] *= r;

            if (it == NLAYERS - 1) {
                float* o = out + ((size_t)b * NQ + q) * KW;
                #pragma unroll
                for (int k = 0; k < KW; k++) o[k] = u[k];
            } else {
                #pragma unroll
                for (int k = 0; k < KW; k++) U_s[q * PADU + k] = u[k];
            }
        }
        if (it == NLAYERS - 1) break;
        __syncthreads();

        // matvec: gu[k] = sum_qp G[q][qp] * U[qp][k]   (thread-per-q)
        if (q < NQ) {
            float ng0 = 0.f, ng1 = 0.f, ng2 = 0.f, ng3 = 0.f, ng4 = 0.f;
            const float* Grow = &G[q * PADG];
            #pragma unroll 3
            for (int qp = 0; qp < NQ; qp += 5) {
                float  gv[5];
                float4 u4[5];
                float  u5[5];
                #pragma unroll
                for (int j = 0; j < 5; j++) {
                    gv[j] = Grow[qp + j];
                    u4[j] = *(const float4*)&U_s[(qp + j) * PADU];
                    u5[j] = U_s[(qp + j) * PADU + 4];
                }
                #pragma unroll
                for (int j = 0; j < 5; j++) {
                    ng0 += gv[j] * u4[j].x; ng1 += gv[j] * u4[j].y;
                    ng2 += gv[j] * u4[j].z; ng3 += gv[j] * u4[j].w;
                    ng4 += gv[j] * u5[j];
                }
            }
            gu[0] = ng0; gu[1] = ng1; gu[2] = ng2; gu[3] = ng3; gu[4] = ng4;
        }

        // fused in-register class stats: usum_k = sum u ; n_k = sum u*(gu+2*sk)
        if (w < 3) {
            float p[2 * KW];
            #pragma unroll
            for (int k = 0; k < KW; k++) {
                p[k]      = u[k];
                p[KW + k] = u[k] * (gu[k] + 2.f * sk[k]);
            }
            #pragma unroll
            for (int o = 16; o > 0; o >>= 1)
                #pragma unroll
                for (int i = 0; i < 2 * KW; i++)
                    p[i] += __shfl_down_sync(0xffffffffu, p[i], o);
            if (lane == 0) {
                #pragma unroll
                for (int i = 0; i < 2 * KW; i++) red_s[w][i] = p[i];
            }
        }
        __syncthreads();

        // every thread rebuilds the per-class state locally (no extra barrier)
        #pragma unroll
        for (int k = 0; k < KW; k++) {
            const float usum = red_s[0][k] + red_s[1][k] + red_s[2][k];
            const float nacc = red_s[0][KW + k] + red_s[1][KW + k] + red_s[2][KW + k];
            const float den  = usum + cnt_r[k];
            const float iv   = 1.0f / den;
            invden_r[k] = iv;
            halfnn_r[k] = 0.5f * (nacc + ssq_r[k]) * iv * iv;
            gV_r[k]     = g * (logf(usum * (1.0f / NQ) + EPS) + 1.0f);
        }
    }
}

extern "C" void kernel_launch(void* const* d_in, const int* in_sizes, int n_in,
                              void* d_out, int out_size)
{
    const float* Zs = (const float*)d_in[0];
    const int*   Y  = (const int*)  d_in[1];
    const float* Zq = (const float*)d_in[2];
    const float* t1 = (const float*)d_in[3];
    const float* gm = (const float*)d_in[4];
    const float* t2 = (const float*)d_in[5];
    cudaFuncSetAttribute(fewshot_kernel,
                         cudaFuncAttributeMaxDynamicSharedMemorySize, SMEM_BYTES);
    fewshot_kernel<<<NTASK, NTHR, SMEM_BYTES>>>(Zs, Y, Zq, t1, gm, t2, (float*)d_out);
}

// round 17
// speedup vs baseline: 1.1088x; 1.1088x over previous
#include <cuda_runtime.h>
#include <math.h>
#include <stdint.h>

#define NTASK   2000
#define NSUP    25
#define NQ      75
#define DIM     640
#define KW      5
#define NLAYERS 20
#define R       80
#define DC      64
#define NCHUNK  (DIM / DC)
#define PADC    68
#define PADG    81
#define PADU    8
#define EPS     1e-6f
#define NTHR    256
#define NTILES  136
#define TPB     2            // tasks per block

#define ZX_FLOATS  (R * PADC)       // 5440
#define SUP_FLOATS (NSUP * PADC)    // 1700
#define SUP_OFF    (2 * ZX_FLOATS)
#define G_OFF      (2 * ZX_FLOATS + 2 * SUP_FLOATS)   // 14280
#define G_TASK     (R * PADG)                         // 6480
#define SMEM_FLOATS (G_OFF + TPB * G_TASK)            // 27240
#define SMEM_BYTES  (SMEM_FLOATS * 4)                 // 108960
#define UBLK       (2 * NQ * PADU)                    // per-task U_s+GU_s floats (1200)

__device__ __forceinline__ void cpa16(uint32_t dst, const float* src) {
    asm volatile("cp.async.cg.shared.global [%0], [%1], 16;" :: "r"(dst), "l"(src));
}

__global__ __launch_bounds__(NTHR, 2)
void fewshot_kernel(const float* __restrict__ Zs_g,
                    const int*   __restrict__ Y_g,
                    const float* __restrict__ Zq_g,
                    const float* __restrict__ t1_p,
                    const float* __restrict__ gm_p,
                    const float* __restrict__ t2_p,
                    float*       __restrict__ out)
{
    extern __shared__ __align__(16) float smem[];
    float* ZxB[2]  = { smem, smem + ZX_FLOATS };
    float* SupB[2] = { smem + SUP_OFF, smem + SUP_OFF + SUP_FLOATS };
    float* Gbase   = smem + G_OFF;

    __shared__ float invden_s[TPB][KW], halfnn_s[TPB][KW], gV_s[TPB][KW],
                     ssq_s[TPB][KW], cnt_s[TPB][KW];
    __shared__ int   Y_sh[TPB][NSUP];

    const int b0 = blockIdx.x * TPB;
    const int t  = threadIdx.x;

    const float c      = log1pf(expf(t1_p[0]));
    const float c2     = c * c;
    const float g      = log1pf(expf(gm_p[0]));
    const float inv_t2 = 1.0f / (log1pf(expf(t2_p[0])) + 1.0f);

    if (t < TPB * NSUP)
        Y_sh[t / NSUP][t % NSUP] = Y_g[(b0 + t / NSUP) * NSUP + (t % NSUP)];

    const uint32_t zx_u32[2]  = { (uint32_t)__cvta_generic_to_shared(ZxB[0]),
                                  (uint32_t)__cvta_generic_to_shared(ZxB[1]) };
    const uint32_t sup_u32[2] = { (uint32_t)__cvta_generic_to_shared(SupB[0]),
                                  (uint32_t)__cvta_generic_to_shared(SupB[1]) };

    // symmetric tile unrank (upper triangle of 16x16 grid of 5x5 tiles)
    const bool act = (t < NTILES);
    int ti = 0, tj = 0;
    {
        int rem = act ? t : 0;
        #pragma unroll
        for (int r = 0; r < 16; r++)
            if (rem >= 16 - ti) { rem -= 16 - ti; ti++; }
        tj = ti + rem;
    }
    const int ri = ti * 5, rj = tj * 5;

    // ================= Phase 1: Gram for each of the two tasks =================
    for (int tk = 0; tk < TPB; tk++) {
        const float* Zq_b = Zq_g + (size_t)(b0 + tk) * NQ   * DIM;
        const float* Zs_b = Zs_g + (size_t)(b0 + tk) * NSUP * DIM;
        float* Gt = Gbase + tk * G_TASK;

        unsigned long long acc[25];
        #pragma unroll
        for (int i = 0; i < 25; i++) acc[i] = 0ull;

        // stage chunk 0
        for (int idx = t; idx < NQ * 16; idx += NTHR) {
            const int row = idx >> 4, v = idx & 15;
            cpa16(zx_u32[0] + (row * PADC + 4 * v) * 4, Zq_b + row * DIM + 4 * v);
        }
        for (int idx = t; idx < NSUP * 16; idx += NTHR) {
            const int row = idx >> 4, v = idx & 15;
            cpa16(sup_u32[0] + (row * PADC + 4 * v) * 4, Zs_b + row * DIM + 4 * v);
        }
        asm volatile("cp.async.commit_group;");

        for (int ch = 0; ch < NCHUNK; ch++) {
            const int cur = ch & 1, nxt = (ch + 1) & 1;
            if (ch + 1 < NCHUNK) {
                const int d0 = (ch + 1) * DC;
                for (int idx = t; idx < NQ * 16; idx += NTHR) {
                    const int row = idx >> 4, v = idx & 15;
                    cpa16(zx_u32[nxt] + (row * PADC + 4 * v) * 4, Zq_b + row * DIM + d0 + 4 * v);
                }
                for (int idx = t; idx < NSUP * 16; idx += NTHR) {
                    const int row = idx >> 4, v = idx & 15;
                    cpa16(sup_u32[nxt] + (row * PADC + 4 * v) * 4, Zs_b + row * DIM + d0 + 4 * v);
                }
            }
            asm volatile("cp.async.commit_group;");
            asm volatile("cp.async.wait_group 1;");
            __syncthreads();

            float* Zx  = ZxB[cur];
            float* Sup = SupB[cur];
            for (int idx = t; idx < KW * DC; idx += NTHR) {
                const int dl = idx & (DC - 1);
                const int k  = idx / DC;
                float s = 0.f;
                #pragma unroll
                for (int j = 0; j < NSUP; j++)
                    if (Y_sh[tk][j] == k) s += Sup[j * PADC + dl];
                Zx[(NQ + k) * PADC + dl] = s;
            }
            __syncthreads();

            if (act) {
                #pragma unroll 4
                for (int dl = 0; dl < DC; dl += 2) {
                    unsigned long long av[5], bv[5];
                    #pragma unroll
                    for (int i = 0; i < 5; i++)
                        av[i] = *(const unsigned long long*)&Zx[(ri + i) * PADC + dl];
                    #pragma unroll
                    for (int j = 0; j < 5; j++)
                        bv[j] = *(const unsigned long long*)&Zx[(rj + j) * PADC + dl];
                    #pragma unroll
                    for (int i = 0; i < 5; i++)
                        #pragma unroll
                        for (int j = 0; j < 5; j++)
                            asm("fma.rn.f32x2 %0, %1, %2, %0;"
                                : "+l"(acc[i * 5 + j]) : "l"(av[i]), "l"(bv[j]));
                }
            }
            __syncthreads();
        }

        if (act) {
            #pragma unroll
            for (int i = 0; i < 5; i++)
                #pragma unroll
                for (int j = 0; j < 5; j++) {
                    const unsigned long long x = acc[i * 5 + j];
                    const float lo = __uint_as_float((unsigned)(x & 0xffffffffu));
                    const float hi = __uint_as_float((unsigned)(x >> 32));
                    const float v  = (lo + hi) * c2;
                    Gt[(ri + i) * PADG + (rj + j)] = v;
                    Gt[(rj + j) * PADG + (ri + i)] = v;
                }
        }
        __syncthreads();
    }

    // ================= init per-class state (both tasks) =================
    if (t < TPB * KW) {
        const int task = t / KW, k = t % KW;
        const float* Gt = Gbase + task * G_TASK;
        float cn = 0.f;
        #pragma unroll
        for (int j = 0; j < NSUP; j++) cn += (Y_sh[task][j] == k) ? 1.f : 0.f;
        const float ssq = Gt[(NQ + k) * PADG + (NQ + k)];
        const float iv  = 1.0f / cn;
        cnt_s[task][k]    = cn;
        ssq_s[task][k]    = ssq;
        invden_s[task][k] = iv;
        halfnn_s[task][k] = 0.5f * ssq * iv * iv;
        gV_s[task][k]     = g;
    }
    __syncthreads();

    // ================= Phase 2: both tasks interleaved =================
    const bool qact = (t < TPB * NQ);
    const int  task = qact ? (t / NQ) : 0;
    const int  q    = qact ? (t % NQ) : 0;
    float* Gt   = Gbase + task * G_TASK;
    float* U_s  = smem + task * UBLK;            // aliases ZxB region
    float* GU_s = smem + task * UBLK + NQ * PADU;

    float sk[KW], gu[KW];
    #pragma unroll
    for (int k = 0; k < KW; k++) {
        gu[k] = 0.f;
        sk[k] = qact ? Gt[(NQ + k) * PADG + q] : 0.f;
    }

    const int w = t >> 5, lane = t & 31;

    for (int it = 0; it < NLAYERS; it++) {
        if (qact) {
            float a[KW], m = -1e30f, u[KW];
            #pragma unroll
            for (int k = 0; k < KW; k++) {
                a[k] = inv_t2 * ((gu[k] + sk[k]) * invden_s[task][k]
                                 - halfnn_s[task][k] + gV_s[task][k]);
                m = fmaxf(m, a[k]);
            }
            float ssum = 0.f;
            #pragma unroll
            for (int k = 0; k < KW; k++) { u[k] = __expf(a[k] - m); ssum += u[k]; }
            const float r = 1.0f / ssum;
            #pragma unroll
            for (int k = 0; k < KW; k++) u[k] *= r;

            if (it == NLAYERS - 1) {
                float* o = out + ((size_t)(b0 + task) * NQ + q) * KW;
                #pragma unroll
                for (int k = 0; k < KW; k++) o[k] = u[k];
            } else {
                #pragma unroll
                for (int k = 0; k < KW; k++) U_s[q * PADU + k] = u[k];
            }
        }
        if (it == NLAYERS - 1) break;
        __syncthreads();

        // matvec: gu = Gq @ U  (150 threads active)
        if (qact) {
            float ng0 = 0.f, ng1 = 0.f, ng2 = 0.f, ng3 = 0.f, ng4 = 0.f;
            const float* Grow = &Gt[q * PADG];
            #pragma unroll 3
            for (int qp = 0; qp < NQ; qp += 5) {
                float  gv[5];
                float4 u4[5];
                float  u5[5];
                #pragma unroll
                for (int j = 0; j < 5; j++) {
                    gv[j] = Grow[qp + j];
                    u4[j] = *(const float4*)&U_s[(qp + j) * PADU];
                    u5[j] = U_s[(qp + j) * PADU + 4];
                }
                #pragma unroll
                for (int j = 0; j < 5; j++) {
                    ng0 += gv[j] * u4[j].x; ng1 += gv[j] * u4[j].y;
                    ng2 += gv[j] * u4[j].z; ng3 += gv[j] * u4[j].w;
                    ng4 += gv[j] * u5[j];
                }
            }
            gu[0] = ng0; gu[1] = ng1; gu[2] = ng2; gu[3] = ng3; gu[4] = ng4;
            GU_s[q * PADU + 0] = ng0; GU_s[q * PADU + 1] = ng1;
            GU_s[q * PADU + 2] = ng2; GU_s[q * PADU + 3] = ng3;
            GU_s[q * PADU + 4] = ng4;
        }
        __syncthreads();

        // class reductions: 10 (task,k) pairs over 8 warps
        for (int p = w; p < TPB * KW; p += 8) {
            const int ptask = p / KW, k = p % KW;
            const float* Gp  = Gbase + ptask * G_TASK;
            const float* Up  = smem + ptask * UBLK;
            const float* GUp = Up + NQ * PADU;
            float usum = 0.f, ups = 0.f, ugu = 0.f;
            for (int qq = lane; qq < NQ; qq += 32) {
                const float uv = Up[qq * PADU + k];
                usum += uv;
                ups  += uv * Gp[(NQ + k) * PADG + qq];
                ugu  += uv * GUp[qq * PADU + k];
            }
            #pragma unroll
            for (int o = 16; o > 0; o >>= 1) {
                usum += __shfl_down_sync(0xffffffffu, usum, o);
                ups  += __shfl_down_sync(0xffffffffu, ups,  o);
                ugu  += __shfl_down_sync(0xffffffffu, ugu,  o);
            }
            if (lane == 0) {
                const float den = usum + cnt_s[ptask][k];
                const float iv  = 1.0f / den;
                const float nn  = ugu + 2.f * ups + ssq_s[ptask][k];
                invden_s[ptask][k] = iv;
                halfnn_s[ptask][k] = 0.5f * nn * iv * iv;
                gV_s[ptask][k]     = g * (logf(usum * (1.0f / NQ) + EPS) + 1.0f);
            }
        }
        __syncthreads();
    }
}

extern "C" void kernel_launch(void* const* d_in, const int* in_sizes, int n_in,
                              void* d_out, int out_size)
{
    const float* Zs = (const float*)d_in[0];
    const int*   Y  = (const int*)  d_in[1];
    const float* Zq = (const float*)d_in[2];
    const float* t1 = (const float*)d_in[3];
    const float* gm = (const float*)d_in[4];
    const float* t2 = (const float*)d_in[5];
    cudaFuncSetAttribute(fewshot_kernel,
                         cudaFuncAttributeMaxDynamicSharedMemorySize, SMEM_BYTES);
    fewshot_kernel<<<NTASK / TPB, NTHR, SMEM_BYTES>>>(Zs, Y, Zq, t1, gm, t2, (float*)d_out);
}